// round 16
// baseline (speedup 1.0000x reference)
#include <cuda_runtime.h>
#include <cstdint>

// Problem constants (fixed by the benchmark's setup_inputs)
#define BB 64
#define LL 4096
#define EE 64
#define SS 45          // sample_k == u == 45
#define NT 32          // cumsum tiles per sequence
#define TILE 128       // LL / NT
#define NKT 4          // k-tiles for attn@V partials

#define NCH 16         // key chunks for the M-score phase
#define CROWS 256      // rows per chunk (LL / NCH)
#define KPAD 68        // padded smem row stride (floats)
#define EMAX 12800     // entry capacity per chunk (mean 11520, sd ~104)

#define NEG_INF (-3.402823466e+38f)

// ---------------- scratch (static device globals) ---------------------------
__device__ int   d_Mtop[BB * 64];
__device__ float d_scores[(size_t)BB * 48 * LL];       // 50 MB
__device__ float d_updp[NKT * BB * SS * EE];
__device__ float d_tsum[BB * NT * EE];
__device__ float d_toff[BB * NT * EE];

__device__ int           d_cnt[NCH * LL];              // samples of l in chunk c
__device__ int           d_base[NCH * LL];             // CSR base (excl. prefix)
__device__ unsigned char d_ent[NCH][EMAX];             // local row ids (0..255)
__device__ uint2         d_srt[NCH * LL];              // count-sorted (base, l|cnt<<16)
__device__ float         d_pmax[(size_t)NCH * BB * LL];
__device__ float         d_psum[(size_t)NCH * BB * LL];

// ============================================================================
// P1: per-(chunk,l) sample counts. Batch-independent.
// ============================================================================
__global__ __launch_bounds__(256) void kP1(const int* __restrict__ idx) {
    int l = blockIdx.x * 256 + threadIdx.x;
    if (l >= LL) return;
    const int* il = idx + (size_t)l * SS;
    unsigned long long pk0 = 0, pk1 = 0;        // 16 packed 8-bit counters
#pragma unroll
    for (int s = 0; s < SS; s++) {
        int c = il[s] >> 8;                     // 0..15
        if (c < 8) pk0 += 1ull << (c * 8);
        else       pk1 += 1ull << ((c - 8) * 8);
    }
#pragma unroll
    for (int c = 0; c < 8; c++) {
        d_cnt[c * LL + l]       = (int)((pk0 >> (c * 8)) & 255ull);
        d_cnt[(c + 8) * LL + l] = (int)((pk1 >> (c * 8)) & 255ull);
    }
}

// ============================================================================
// P2: per-chunk exclusive prefix over l (Hillis-Steele on 1024 thread sums).
// ============================================================================
__global__ __launch_bounds__(1024) void kP2() {
    __shared__ int sh[1024];
    int c = blockIdx.x, t = threadIdx.x;
    int v0 = d_cnt[c * LL + t * 4 + 0];
    int v1 = d_cnt[c * LL + t * 4 + 1];
    int v2 = d_cnt[c * LL + t * 4 + 2];
    int v3 = d_cnt[c * LL + t * 4 + 3];
    int ts = v0 + v1 + v2 + v3;
    sh[t] = ts;
    __syncthreads();
    for (int off = 1; off < 1024; off <<= 1) {
        int x = (t >= off) ? sh[t - off] : 0;
        __syncthreads();
        sh[t] += x;
        __syncthreads();
    }
    int excl = sh[t] - ts;
    d_base[c * LL + t * 4 + 0] = excl;
    d_base[c * LL + t * 4 + 1] = excl + v0;
    d_base[c * LL + t * 4 + 2] = excl + v0 + v1;
    d_base[c * LL + t * 4 + 3] = excl + v0 + v1 + v2;
}

// ============================================================================
// P3: scatter entries (local row ids) into the per-chunk CSR lists.
// ============================================================================
__global__ __launch_bounds__(256) void kP3(const int* __restrict__ idx) {
    int l = blockIdx.x * 256 + threadIdx.x;
    if (l >= LL) return;
    int off[NCH];
#pragma unroll
    for (int c = 0; c < NCH; c++) off[c] = d_base[c * LL + l];
    const int* il = idx + (size_t)l * SS;
#pragma unroll
    for (int s = 0; s < SS; s++) {
        int j = il[s];
        int c = j >> 8;
        d_ent[c][off[c]++] = (unsigned char)(j & 255);
    }
}

// ============================================================================
// kS: per-chunk counting sort of l's by cnt (ascending). Final M output is
// invariant to processing order, so atomic rank assignment stays correct.
// ============================================================================
__global__ __launch_bounds__(512) void kS() {
    __shared__ int hist[64];
    __shared__ int off[64];
    int c = blockIdx.x, t = threadIdx.x;
    if (t < 64) hist[t] = 0;
    __syncthreads();
    for (int l = t; l < LL; l += 512) atomicAdd(&hist[d_cnt[c * LL + l]], 1);
    __syncthreads();
    if (t == 0) {
        int acc = 0;
        for (int i = 0; i < 64; i++) { off[i] = acc; acc += hist[i]; }
    }
    __syncthreads();
    for (int l = t; l < LL; l += 512) {
        int cnt = d_cnt[c * LL + l];
        int r = atomicAdd(&off[cnt], 1);
        d_srt[c * LL + r] =
            make_uint2((unsigned)d_base[c * LL + l],
                       (unsigned)l | ((unsigned)cnt << 16));
    }
}

// ============================================================================
// kA2: per-(chunk,b) partial M stats. 256-row key chunk in smem (69.6KB ->
// 2 CTAs/SM). Conflict-free lane mapping; dual-l pipeline per 8-lane group.
// Champion version (round 7/9) -- untouched.
// grid (NCH, BB, 2), 512 threads.
// ============================================================================
extern __shared__ float ks[];
__global__ __launch_bounds__(512, 2) void kA2(const float* __restrict__ q,
                                              const float* __restrict__ k) {
    int c = blockIdx.x, b = blockIdx.y, z = blockIdx.z;
    int t = threadIdx.x;

    const float* kb = k + ((size_t)b * LL + c * CROWS) * EE;
    for (int i = t; i < CROWS * EE; i += 512) {
        int r = i >> 6, e = i & 63;
        ks[r * KPAD + e] = kb[i];
    }
    __syncthreads();

    const unsigned char* sent = d_ent[c];
    int g = t >> 3, lg = t & 7;                     // 64 groups of 8 lanes
    int eo0 = lg * 4, eo1 = 32 + lg * 4;            // conflict-free e offsets
    float* pmax = d_pmax + ((size_t)c * BB + b) * LL;
    float* psum = d_psum + ((size_t)c * BB + b) * LL;

    int zbase = z * 2048;
    for (int m = 0; m < 16; m++) {
        int r0 = zbase + (g << 1) + (m << 7);
        uint2 s0 = d_srt[c * LL + r0];
        uint2 s1 = d_srt[c * LL + r0 + 1];
        int base0 = (int)s0.x, l0 = (int)(s0.y & 0xFFFFu), cnt0 = (int)(s0.y >> 16);
        int base1 = (int)s1.x, l1 = (int)(s1.y & 0xFFFFu), cnt1 = (int)(s1.y >> 16);

        int mc = max(cnt0, cnt1);                   // warp-uniform bound
        mc = max(mc, __shfl_xor_sync(0xffffffffu, mc, 8));
        mc = max(mc, __shfl_xor_sync(0xffffffffu, mc, 16));

        float mx0 = NEG_INF, sm0 = 0.0f;
        float mx1 = NEG_INF, sm1 = 0.0f;
        if (mc > 0) {
            const float* q0 = q + ((size_t)b * LL + l0) * EE;
            const float* q1 = q + ((size_t)b * LL + l1) * EE;
            float4 qa0 = *(const float4*)(q0 + eo0);
            float4 qb0 = *(const float4*)(q0 + eo1);
            float4 qa1 = *(const float4*)(q1 + eo0);
            float4 qb1 = *(const float4*)(q1 + eo1);
#pragma unroll 2
            for (int e = 0; e < mc; e++) {
                int ei0 = base0 + ((e < cnt0) ? e : 0);
                int ei1 = base1 + ((e < cnt1) ? e : 0);
                int jr0 = sent[ei0];
                int jr1 = sent[ei1];
                const float* kr0 = &ks[jr0 * KPAD];
                const float* kr1 = &ks[jr1 * KPAD];
                float4 ka0 = *(const float4*)(kr0 + eo0);
                float4 kb0 = *(const float4*)(kr0 + eo1);
                float4 ka1 = *(const float4*)(kr1 + eo0);
                float4 kb1 = *(const float4*)(kr1 + eo1);

                float pa0 = qa0.x * ka0.x;
                float pb0 = qb0.x * kb0.x;
                pa0 = fmaf(qa0.y, ka0.y, pa0);
                pb0 = fmaf(qb0.y, kb0.y, pb0);
                pa0 = fmaf(qa0.z, ka0.z, pa0);
                pb0 = fmaf(qb0.z, kb0.z, pb0);
                pa0 = fmaf(qa0.w, ka0.w, pa0);
                pb0 = fmaf(qb0.w, kb0.w, pb0);
                float p0 = pa0 + pb0;

                float pa1 = qa1.x * ka1.x;
                float pb1 = qb1.x * kb1.x;
                pa1 = fmaf(qa1.y, ka1.y, pa1);
                pb1 = fmaf(qb1.y, kb1.y, pb1);
                pa1 = fmaf(qa1.z, ka1.z, pa1);
                pb1 = fmaf(qb1.z, kb1.z, pb1);
                pa1 = fmaf(qa1.w, ka1.w, pa1);
                pb1 = fmaf(qb1.w, kb1.w, pb1);
                float p1 = pa1 + pb1;

                float u0 = __shfl_xor_sync(0xffffffffu, p0, 1);
                float u1 = __shfl_xor_sync(0xffffffffu, p1, 1);
                p0 += u0; p1 += u1;
                u0 = __shfl_xor_sync(0xffffffffu, p0, 2);
                u1 = __shfl_xor_sync(0xffffffffu, p1, 2);
                p0 += u0; p1 += u1;
                u0 = __shfl_xor_sync(0xffffffffu, p0, 4);
                u1 = __shfl_xor_sync(0xffffffffu, p1, 4);
                p0 += u0; p1 += u1;

                if (e < cnt0) { mx0 = fmaxf(mx0, p0); sm0 += p0; }
                if (e < cnt1) { mx1 = fmaxf(mx1, p1); sm1 += p1; }
            }
        }
        if (lg == 0) {
            pmax[l0] = mx0; psum[l0] = sm0;
            pmax[l1] = mx1; psum[l1] = sm1;
        }
    }
}

// ============================================================================
// kB: per-batch top-45. The A3 combine (chunk partials -> M) is fused into
// the smem staging loop.
// ============================================================================
__global__ __launch_bounds__(1024) void kB() {
    __shared__ float sv[LL];
    __shared__ float wmax[32];
    __shared__ int   widx[32];
    int b = blockIdx.x, t = threadIdx.x;

    for (int i = t; i < LL; i += 1024) {
        float mx = NEG_INF, sm = 0.0f;
#pragma unroll
        for (int c = 0; c < NCH; c++) {
            mx = fmaxf(mx, d_pmax[((size_t)c * BB + b) * LL + i]);
            sm += d_psum[((size_t)c * BB + b) * LL + i];
        }
        sv[i] = mx - sm * (1.0f / (float)LL);
    }
    __syncthreads();

    for (int it = 0; it < SS; it++) {
        float best = NEG_INF;
        int   bi   = LL;
        for (int i = t; i < LL; i += 1024) {
            float vv = sv[i];
            if (vv > best) { best = vv; bi = i; }
        }
#pragma unroll
        for (int o = 16; o > 0; o >>= 1) {
            float ov = __shfl_down_sync(0xffffffffu, best, o);
            int   oi = __shfl_down_sync(0xffffffffu, bi, o);
            if (ov > best || (ov == best && oi < bi)) { best = ov; bi = oi; }
        }
        if ((t & 31) == 0) { wmax[t >> 5] = best; widx[t >> 5] = bi; }
        __syncthreads();
        if (t < 32) {
            float bv = wmax[t];
            int   bj = widx[t];
#pragma unroll
            for (int o = 16; o > 0; o >>= 1) {
                float ov = __shfl_down_sync(0xffffffffu, bv, o);
                int   oi = __shfl_down_sync(0xffffffffu, bj, o);
                if (ov > bv || (ov == bv && oi < bj)) { bv = ov; bj = oi; }
            }
            if (t == 0) {
                d_Mtop[b * 64 + it] = bj;
                sv[bj] = NEG_INF;
            }
        }
        __syncthreads();
    }
}

// ============================================================================
// kC1: scores[b,u,k] = (q[b, Mtop[b,u]] . keys[b,k]) * scale
// 4 independent accumulator chains per dot.
// ============================================================================
__global__ __launch_bounds__(128) void kC1(const float* __restrict__ q,
                                           const float* __restrict__ k) {
    __shared__ float qs[SS * EE];
    int b = blockIdx.y, t = threadIdx.x;

    for (int i = t; i < SS * EE; i += 128) {
        int u = i >> 6, e = i & 63;
        int row = d_Mtop[b * 64 + u];
        qs[i] = q[((size_t)b * LL + row) * EE + e];
    }
    __syncthreads();

    int kk = blockIdx.x * 128 + t;
    const float4* kr = reinterpret_cast<const float4*>(k + ((size_t)b * LL + kk) * EE);
    float4 kv[16];
#pragma unroll
    for (int i = 0; i < 16; i++) kv[i] = kr[i];

    const float scale = 0.125f;
    float* srow = d_scores + (size_t)b * SS * LL + kk;
    const float4* qs4 = reinterpret_cast<const float4*>(qs);
#pragma unroll 1
    for (int u = 0; u < SS; u++) {
        float d0 = 0.0f, d1 = 0.0f, d2 = 0.0f, d3 = 0.0f;
#pragma unroll
        for (int i = 0; i < 4; i++) {
            float4 q0 = qs4[u * 16 + i];
            float4 q1 = qs4[u * 16 + 4 + i];
            float4 q2 = qs4[u * 16 + 8 + i];
            float4 q3 = qs4[u * 16 + 12 + i];
            d0 = fmaf(q0.x, kv[i].x, d0);
            d1 = fmaf(q1.x, kv[4 + i].x, d1);
            d2 = fmaf(q2.x, kv[8 + i].x, d2);
            d3 = fmaf(q3.x, kv[12 + i].x, d3);
            d0 = fmaf(q0.y, kv[i].y, d0);
            d1 = fmaf(q1.y, kv[4 + i].y, d1);
            d2 = fmaf(q2.y, kv[8 + i].y, d2);
            d3 = fmaf(q3.y, kv[12 + i].y, d3);
            d0 = fmaf(q0.z, kv[i].z, d0);
            d1 = fmaf(q1.z, kv[4 + i].z, d1);
            d2 = fmaf(q2.z, kv[8 + i].z, d2);
            d3 = fmaf(q3.z, kv[12 + i].z, d3);
            d0 = fmaf(q0.w, kv[i].w, d0);
            d1 = fmaf(q1.w, kv[4 + i].w, d1);
            d2 = fmaf(q2.w, kv[8 + i].w, d2);
            d3 = fmaf(q3.w, kv[12 + i].w, d3);
        }
        srow[(size_t)u * LL] = ((d0 + d1) + (d2 + d3)) * scale;
    }
}

// ============================================================================
// kC2: in-place softmax over k for each (b,u) row. One block per row.
// 512 threads (was 256): per-thread serial chain halved to 8 elements.
// ============================================================================
__global__ __launch_bounds__(512) void kC2() {
    __shared__ float red[512];
    int t = threadIdx.x;
    float* row = d_scores + (size_t)blockIdx.x * LL;

    float vreg[8];
    float mx = NEG_INF;
#pragma unroll
    for (int i = 0; i < 8; i++) {
        vreg[i] = row[t + i * 512];
        mx = fmaxf(mx, vreg[i]);
    }
    red[t] = mx;
    __syncthreads();
#pragma unroll
    for (int o = 256; o > 0; o >>= 1) {
        if (t < o) red[t] = fmaxf(red[t], red[t + o]);
        __syncthreads();
    }
    float m = red[0];
    __syncthreads();

    float s = 0.0f;
#pragma unroll
    for (int i = 0; i < 8; i++) {
        vreg[i] = __expf(vreg[i] - m);
        s += vreg[i];
    }
    red[t] = s;
    __syncthreads();
#pragma unroll
    for (int o = 256; o > 0; o >>= 1) {
        if (t < o) red[t] += red[t + o];
        __syncthreads();
    }
    float inv = 1.0f / red[0];
#pragma unroll
    for (int i = 0; i < 8; i++) row[t + i * 512] = vreg[i] * inv;
}

// ============================================================================
// kC3: partial upd[kt][b,u,e] over a contiguous k-range; deterministic smem
// reduction across the 4 kg groups. Pure FMA streaming.
// ============================================================================
__global__ __launch_bounds__(256) void kC3(const float* __restrict__ v) {
    __shared__ float sred[SS * EE];
    int b = blockIdx.x;
    int t = threadIdx.x;
    int e = t & 63, kg = t >> 6;
    int kbase = blockIdx.y * (LL / NKT) + kg * 256;

    const float* attn = d_scores + (size_t)b * SS * LL;
    const float* vb = v + (size_t)b * LL * EE;

    float acc[SS];
#pragma unroll
    for (int u = 0; u < SS; u++) acc[u] = 0.0f;

    for (int kb2 = 0; kb2 < 256; kb2 += 4) {
        int k0 = kbase + kb2;
        float vv0 = vb[(size_t)(k0 + 0) * EE + e];
        float vv1 = vb[(size_t)(k0 + 1) * EE + e];
        float vv2 = vb[(size_t)(k0 + 2) * EE + e];
        float vv3 = vb[(size_t)(k0 + 3) * EE + e];
#pragma unroll
        for (int u = 0; u < SS; u++) {
            float4 a4 = *reinterpret_cast<const float4*>(&attn[(size_t)u * LL + k0]);
            float r = acc[u];
            r = fmaf(a4.x, vv0, r);
            r = fmaf(a4.y, vv1, r);
            r = fmaf(a4.z, vv2, r);
            r = fmaf(a4.w, vv3, r);
            acc[u] = r;
        }
    }

    if (kg == 0) {
#pragma unroll
        for (int u = 0; u < SS; u++) sred[u * 64 + e] = acc[u];
    }
    __syncthreads();
    for (int r = 1; r < 4; r++) {
        if (kg == r) {
#pragma unroll
            for (int u = 0; u < SS; u++) sred[u * 64 + e] += acc[u];
        }
        __syncthreads();
    }
    float* outp = d_updp + (((size_t)blockIdx.y * BB + b) * SS) * EE;
    for (int i = t; i < SS * EE; i += 256) outp[i] = sred[i];
}

// ============================================================================
// kD1: per-tile column sums of values (scan phase 1).
// ============================================================================
__global__ __launch_bounds__(256) void kD1(const float* __restrict__ v) {
    __shared__ float sred[2 * EE];
    int b = blockIdx.x, tile = blockIdx.y, t = threadIdx.x;
    int e = t & 63, g = t >> 6;
    const float* vp = v + ((size_t)b * LL + tile * TILE + g * (TILE / 4)) * EE + e;

    float s = 0.0f;
#pragma unroll 8
    for (int i = 0; i < TILE / 4; i++) s += vp[(size_t)i * EE];
    if (g >= 2) sred[(g - 2) * EE + e] = s;
    __syncthreads();
    if (g < 2) sred[g * EE + e] += s;
    __syncthreads();
    if (g == 0) {
        float tot = sred[e] + sred[EE + e];
        d_tsum[((size_t)b * NT + tile) * EE + e] = tot;
    }
}

// ============================================================================
// kD2: exclusive scan of tile sums (scan phase 2). grid BB, 64 threads.
// ============================================================================
__global__ __launch_bounds__(64) void kD2() {
    int b = blockIdx.x, e = threadIdx.x;
    float acc = 0.0f;
    for (int tt = 0; tt < NT; tt++) {
        float s = d_tsum[((size_t)b * NT + tt) * EE + e];
        d_toff[((size_t)b * NT + tt) * EE + e] = acc;
        acc += s;
    }
}

// ============================================================================
// kD3: within-tile inclusive scan + precomputed offset -> out.
// ============================================================================
__global__ __launch_bounds__(64) void kD3(const float* __restrict__ v,
                                          float* __restrict__ out) {
    int b = blockIdx.x, tile = blockIdx.y, e = threadIdx.x;

    float acc = d_toff[((size_t)b * NT + tile) * EE + e];

    const float* vp = v + ((size_t)b * LL + tile * TILE) * EE + e;
    float* op = out + ((size_t)b * LL + tile * TILE) * EE + e;

    for (int i = 0; i < TILE; i += 8) {
        float x[8];
#pragma unroll
        for (int j = 0; j < 8; j++) x[j] = vp[(size_t)(i + j) * EE];
#pragma unroll
        for (int j = 0; j < 8; j++) { acc += x[j]; x[j] = acc; }
#pragma unroll
        for (int j = 0; j < 8; j++) op[(size_t)(i + j) * EE] = x[j];
    }
}

// ============================================================================
// kE: sum the NKT upd partials and scatter into out at the top-k rows.
// ============================================================================
__global__ __launch_bounds__(64) void kE(float* __restrict__ out) {
    int bu = blockIdx.x;
    int b = bu / SS, u = bu % SS;
    int e = threadIdx.x;
    int row = d_Mtop[b * 64 + u];

    float s = 0.0f;
#pragma unroll
    for (int kt = 0; kt < NKT; kt++)
        s += d_updp[(((size_t)kt * BB + b) * SS + u) * EE + e];

    out[((size_t)b * LL + row) * EE + e] = s;
}

// ============================================================================
extern "C" void kernel_launch(void* const* d_in, const int* in_sizes, int n_in,
                              void* d_out, int out_size) {
    const float* q   = (const float*)d_in[0];
    const float* k   = (const float*)d_in[1];
    const float* v   = (const float*)d_in[2];
    const int*   idx = (const int*)d_in[3];
    float* out = (float*)d_out;

    const int smemA2 = CROWS * KPAD * 4;   // 69632 bytes -> 2 CTAs/SM
    static int cfg_done = 0;
    if (!cfg_done) {
        cudaFuncSetAttribute(kA2, cudaFuncAttributeMaxDynamicSharedMemorySize,
                             smemA2);
        cfg_done = 1;
    }

    static cudaStream_t sD = nullptr;
    static cudaEvent_t  evFork = nullptr, evJoin = nullptr;
    if (!sD) {
        cudaStreamCreateWithFlags(&sD, cudaStreamNonBlocking);
        cudaEventCreateWithFlags(&evFork, cudaEventDisableTiming);
        cudaEventCreateWithFlags(&evJoin, cudaEventDisableTiming);
    }

    // Fork the independent cumsum chain at launch start: it overlaps the tiny
    // latency-bound P-phase kernels and finishes around when kA2 starts.
    cudaEventRecord(evFork, 0);
    cudaStreamWaitEvent(sD, evFork, 0);
    kD1<<<dim3(BB, NT), 256, 0, sD>>>(v);
    kD2<<<BB, 64, 0, sD>>>();
    kD3<<<dim3(BB, NT), 64, 0, sD>>>(v, out);
    cudaEventRecord(evJoin, sD);

    // Main chain.
    kP1<<<LL / 256, 256>>>(idx);
    kP2<<<NCH, 1024>>>();
    kP3<<<LL / 256, 256>>>(idx);
    kS<<<NCH, 512>>>();
    kA2<<<dim3(NCH, BB, 2), 512, smemA2>>>(q, k);
    kB<<<BB, 1024>>>();
    kC1<<<dim3(LL / 128, BB), 128>>>(q, k);
    kC2<<<BB * SS, 512>>>();
    kC3<<<dim3(BB, NKT), 256>>>(v);

    cudaStreamWaitEvent(0, evJoin, 0);
    kE<<<BB * SS, 64>>>(out);
}

// round 17
// speedup vs baseline: 1.0065x; 1.0065x over previous
#include <cuda_runtime.h>
#include <cstdint>

// Problem constants (fixed by the benchmark's setup_inputs)
#define BB 64
#define LL 4096
#define EE 64
#define SS 45          // sample_k == u == 45
#define NT 32          // cumsum tiles per sequence
#define TILE 128       // LL / NT
#define NKT 4          // k-tiles for attn@V partials

#define NCH 16         // key chunks for the M-score phase
#define CROWS 256      // rows per chunk (LL / NCH)
#define KPAD 68        // padded smem row stride (floats)
#define EMAX 12800     // entry capacity per chunk (mean 11520, sd ~104)

#define NEG_INF (-3.402823466e+38f)

// ---------------- scratch (static device globals) ---------------------------
__device__ int   d_Mtop[BB * 64];
__device__ float d_scores[(size_t)BB * 48 * LL];       // 50 MB
__device__ float d_updp[NKT * BB * SS * EE];
__device__ float d_tsum[BB * NT * EE];
__device__ float d_toff[BB * NT * EE];

__device__ int           d_cnt[NCH * LL];              // samples of l in chunk c
__device__ int           d_base[NCH * LL];             // CSR base (excl. prefix)
__device__ unsigned char d_ent[NCH][EMAX];             // local row ids (0..255)
__device__ uint2         d_srt[NCH * LL];              // count-sorted (base, l|cnt<<16)
__device__ float         d_pmax[(size_t)NCH * BB * LL];
__device__ float         d_psum[(size_t)NCH * BB * LL];

// ============================================================================
// P1: per-(chunk,l) sample counts. Batch-independent.
// ============================================================================
__global__ __launch_bounds__(256) void kP1(const int* __restrict__ idx) {
    int l = blockIdx.x * 256 + threadIdx.x;
    if (l >= LL) return;
    const int* il = idx + (size_t)l * SS;
    unsigned long long pk0 = 0, pk1 = 0;        // 16 packed 8-bit counters
#pragma unroll
    for (int s = 0; s < SS; s++) {
        int c = il[s] >> 8;                     // 0..15
        if (c < 8) pk0 += 1ull << (c * 8);
        else       pk1 += 1ull << ((c - 8) * 8);
    }
#pragma unroll
    for (int c = 0; c < 8; c++) {
        d_cnt[c * LL + l]       = (int)((pk0 >> (c * 8)) & 255ull);
        d_cnt[(c + 8) * LL + l] = (int)((pk1 >> (c * 8)) & 255ull);
    }
}

// ============================================================================
// P2: per-chunk exclusive prefix over l (Hillis-Steele on 1024 thread sums).
// ============================================================================
__global__ __launch_bounds__(1024) void kP2() {
    __shared__ int sh[1024];
    int c = blockIdx.x, t = threadIdx.x;
    int v0 = d_cnt[c * LL + t * 4 + 0];
    int v1 = d_cnt[c * LL + t * 4 + 1];
    int v2 = d_cnt[c * LL + t * 4 + 2];
    int v3 = d_cnt[c * LL + t * 4 + 3];
    int ts = v0 + v1 + v2 + v3;
    sh[t] = ts;
    __syncthreads();
    for (int off = 1; off < 1024; off <<= 1) {
        int x = (t >= off) ? sh[t - off] : 0;
        __syncthreads();
        sh[t] += x;
        __syncthreads();
    }
    int excl = sh[t] - ts;
    d_base[c * LL + t * 4 + 0] = excl;
    d_base[c * LL + t * 4 + 1] = excl + v0;
    d_base[c * LL + t * 4 + 2] = excl + v0 + v1;
    d_base[c * LL + t * 4 + 3] = excl + v0 + v1 + v2;
}

// ============================================================================
// P3: scatter entries (local row ids) into the per-chunk CSR lists.
// ============================================================================
__global__ __launch_bounds__(256) void kP3(const int* __restrict__ idx) {
    int l = blockIdx.x * 256 + threadIdx.x;
    if (l >= LL) return;
    int off[NCH];
#pragma unroll
    for (int c = 0; c < NCH; c++) off[c] = d_base[c * LL + l];
    const int* il = idx + (size_t)l * SS;
#pragma unroll
    for (int s = 0; s < SS; s++) {
        int j = il[s];
        int c = j >> 8;
        d_ent[c][off[c]++] = (unsigned char)(j & 255);
    }
}

// ============================================================================
// kS: per-chunk counting sort of l's by cnt (ascending). Final M output is
// invariant to processing order, so atomic rank assignment stays correct.
// ============================================================================
__global__ __launch_bounds__(512) void kS() {
    __shared__ int hist[64];
    __shared__ int off[64];
    int c = blockIdx.x, t = threadIdx.x;
    if (t < 64) hist[t] = 0;
    __syncthreads();
    for (int l = t; l < LL; l += 512) atomicAdd(&hist[d_cnt[c * LL + l]], 1);
    __syncthreads();
    if (t == 0) {
        int acc = 0;
        for (int i = 0; i < 64; i++) { off[i] = acc; acc += hist[i]; }
    }
    __syncthreads();
    for (int l = t; l < LL; l += 512) {
        int cnt = d_cnt[c * LL + l];
        int r = atomicAdd(&off[cnt], 1);
        d_srt[c * LL + r] =
            make_uint2((unsigned)d_base[c * LL + l],
                       (unsigned)l | ((unsigned)cnt << 16));
    }
}

// ============================================================================
// kA2: per-(chunk,b) partial M stats. 256-row key chunk in smem (69.6KB ->
// 2 CTAs/SM). Conflict-free lane mapping; dual-l pipeline per 8-lane group.
// Champion version.
// grid (NCH, BB, 2), 512 threads.
// ============================================================================
extern __shared__ float ks[];
__global__ __launch_bounds__(512, 2) void kA2(const float* __restrict__ q,
                                              const float* __restrict__ k) {
    int c = blockIdx.x, b = blockIdx.y, z = blockIdx.z;
    int t = threadIdx.x;

    const float* kb = k + ((size_t)b * LL + c * CROWS) * EE;
    for (int i = t; i < CROWS * EE; i += 512) {
        int r = i >> 6, e = i & 63;
        ks[r * KPAD + e] = kb[i];
    }
    __syncthreads();

    const unsigned char* sent = d_ent[c];
    int g = t >> 3, lg = t & 7;                     // 64 groups of 8 lanes
    int eo0 = lg * 4, eo1 = 32 + lg * 4;            // conflict-free e offsets
    float* pmax = d_pmax + ((size_t)c * BB + b) * LL;
    float* psum = d_psum + ((size_t)c * BB + b) * LL;

    int zbase = z * 2048;
    for (int m = 0; m < 16; m++) {
        int r0 = zbase + (g << 1) + (m << 7);
        uint2 s0 = d_srt[c * LL + r0];
        uint2 s1 = d_srt[c * LL + r0 + 1];
        int base0 = (int)s0.x, l0 = (int)(s0.y & 0xFFFFu), cnt0 = (int)(s0.y >> 16);
        int base1 = (int)s1.x, l1 = (int)(s1.y & 0xFFFFu), cnt1 = (int)(s1.y >> 16);

        int mc = max(cnt0, cnt1);                   // warp-uniform bound
        mc = max(mc, __shfl_xor_sync(0xffffffffu, mc, 8));
        mc = max(mc, __shfl_xor_sync(0xffffffffu, mc, 16));

        float mx0 = NEG_INF, sm0 = 0.0f;
        float mx1 = NEG_INF, sm1 = 0.0f;
        if (mc > 0) {
            const float* q0 = q + ((size_t)b * LL + l0) * EE;
            const float* q1 = q + ((size_t)b * LL + l1) * EE;
            float4 qa0 = *(const float4*)(q0 + eo0);
            float4 qb0 = *(const float4*)(q0 + eo1);
            float4 qa1 = *(const float4*)(q1 + eo0);
            float4 qb1 = *(const float4*)(q1 + eo1);
#pragma unroll 2
            for (int e = 0; e < mc; e++) {
                int ei0 = base0 + ((e < cnt0) ? e : 0);
                int ei1 = base1 + ((e < cnt1) ? e : 0);
                int jr0 = sent[ei0];
                int jr1 = sent[ei1];
                const float* kr0 = &ks[jr0 * KPAD];
                const float* kr1 = &ks[jr1 * KPAD];
                float4 ka0 = *(const float4*)(kr0 + eo0);
                float4 kb0 = *(const float4*)(kr0 + eo1);
                float4 ka1 = *(const float4*)(kr1 + eo0);
                float4 kb1 = *(const float4*)(kr1 + eo1);

                float pa0 = qa0.x * ka0.x;
                float pb0 = qb0.x * kb0.x;
                pa0 = fmaf(qa0.y, ka0.y, pa0);
                pb0 = fmaf(qb0.y, kb0.y, pb0);
                pa0 = fmaf(qa0.z, ka0.z, pa0);
                pb0 = fmaf(qb0.z, kb0.z, pb0);
                pa0 = fmaf(qa0.w, ka0.w, pa0);
                pb0 = fmaf(qb0.w, kb0.w, pb0);
                float p0 = pa0 + pb0;

                float pa1 = qa1.x * ka1.x;
                float pb1 = qb1.x * kb1.x;
                pa1 = fmaf(qa1.y, ka1.y, pa1);
                pb1 = fmaf(qb1.y, kb1.y, pb1);
                pa1 = fmaf(qa1.z, ka1.z, pa1);
                pb1 = fmaf(qb1.z, kb1.z, pb1);
                pa1 = fmaf(qa1.w, ka1.w, pa1);
                pb1 = fmaf(qb1.w, kb1.w, pb1);
                float p1 = pa1 + pb1;

                float u0 = __shfl_xor_sync(0xffffffffu, p0, 1);
                float u1 = __shfl_xor_sync(0xffffffffu, p1, 1);
                p0 += u0; p1 += u1;
                u0 = __shfl_xor_sync(0xffffffffu, p0, 2);
                u1 = __shfl_xor_sync(0xffffffffu, p1, 2);
                p0 += u0; p1 += u1;
                u0 = __shfl_xor_sync(0xffffffffu, p0, 4);
                u1 = __shfl_xor_sync(0xffffffffu, p1, 4);
                p0 += u0; p1 += u1;

                if (e < cnt0) { mx0 = fmaxf(mx0, p0); sm0 += p0; }
                if (e < cnt1) { mx1 = fmaxf(mx1, p1); sm1 += p1; }
            }
        }
        if (lg == 0) {
            pmax[l0] = mx0; psum[l0] = sm0;
            pmax[l1] = mx1; psum[l1] = sm1;
        }
    }
}

// ============================================================================
// kB: per-batch top-45. The A3 combine (chunk partials -> M) is fused into
// the smem staging loop.
// ============================================================================
__global__ __launch_bounds__(1024) void kB() {
    __shared__ float sv[LL];
    __shared__ float wmax[32];
    __shared__ int   widx[32];
    int b = blockIdx.x, t = threadIdx.x;

    for (int i = t; i < LL; i += 1024) {
        float mx = NEG_INF, sm = 0.0f;
#pragma unroll
        for (int c = 0; c < NCH; c++) {
            mx = fmaxf(mx, d_pmax[((size_t)c * BB + b) * LL + i]);
            sm += d_psum[((size_t)c * BB + b) * LL + i];
        }
        sv[i] = mx - sm * (1.0f / (float)LL);
    }
    __syncthreads();

    for (int it = 0; it < SS; it++) {
        float best = NEG_INF;
        int   bi   = LL;
        for (int i = t; i < LL; i += 1024) {
            float vv = sv[i];
            if (vv > best) { best = vv; bi = i; }
        }
#pragma unroll
        for (int o = 16; o > 0; o >>= 1) {
            float ov = __shfl_down_sync(0xffffffffu, best, o);
            int   oi = __shfl_down_sync(0xffffffffu, bi, o);
            if (ov > best || (ov == best && oi < bi)) { best = ov; bi = oi; }
        }
        if ((t & 31) == 0) { wmax[t >> 5] = best; widx[t >> 5] = bi; }
        __syncthreads();
        if (t < 32) {
            float bv = wmax[t];
            int   bj = widx[t];
#pragma unroll
            for (int o = 16; o > 0; o >>= 1) {
                float ov = __shfl_down_sync(0xffffffffu, bv, o);
                int   oi = __shfl_down_sync(0xffffffffu, bj, o);
                if (ov > bv || (ov == bv && oi < bj)) { bv = ov; bj = oi; }
            }
            if (t == 0) {
                d_Mtop[b * 64 + it] = bj;
                sv[bj] = NEG_INF;
            }
        }
        __syncthreads();
    }
}

// ============================================================================
// kC1: scores[b,u,k] = (q[b, Mtop[b,u]] . keys[b,k]) * scale
// 4 independent accumulator chains per dot.
// ============================================================================
__global__ __launch_bounds__(128) void kC1(const float* __restrict__ q,
                                           const float* __restrict__ k) {
    __shared__ float qs[SS * EE];
    int b = blockIdx.y, t = threadIdx.x;

    for (int i = t; i < SS * EE; i += 128) {
        int u = i >> 6, e = i & 63;
        int row = d_Mtop[b * 64 + u];
        qs[i] = q[((size_t)b * LL + row) * EE + e];
    }
    __syncthreads();

    int kk = blockIdx.x * 128 + t;
    const float4* kr = reinterpret_cast<const float4*>(k + ((size_t)b * LL + kk) * EE);
    float4 kv[16];
#pragma unroll
    for (int i = 0; i < 16; i++) kv[i] = kr[i];

    const float scale = 0.125f;
    float* srow = d_scores + (size_t)b * SS * LL + kk;
    const float4* qs4 = reinterpret_cast<const float4*>(qs);
#pragma unroll 1
    for (int u = 0; u < SS; u++) {
        float d0 = 0.0f, d1 = 0.0f, d2 = 0.0f, d3 = 0.0f;
#pragma unroll
        for (int i = 0; i < 4; i++) {
            float4 q0 = qs4[u * 16 + i];
            float4 q1 = qs4[u * 16 + 4 + i];
            float4 q2 = qs4[u * 16 + 8 + i];
            float4 q3 = qs4[u * 16 + 12 + i];
            d0 = fmaf(q0.x, kv[i].x, d0);
            d1 = fmaf(q1.x, kv[4 + i].x, d1);
            d2 = fmaf(q2.x, kv[8 + i].x, d2);
            d3 = fmaf(q3.x, kv[12 + i].x, d3);
            d0 = fmaf(q0.y, kv[i].y, d0);
            d1 = fmaf(q1.y, kv[4 + i].y, d1);
            d2 = fmaf(q2.y, kv[8 + i].y, d2);
            d3 = fmaf(q3.y, kv[12 + i].y, d3);
            d0 = fmaf(q0.z, kv[i].z, d0);
            d1 = fmaf(q1.z, kv[4 + i].z, d1);
            d2 = fmaf(q2.z, kv[8 + i].z, d2);
            d3 = fmaf(q3.z, kv[12 + i].z, d3);
            d0 = fmaf(q0.w, kv[i].w, d0);
            d1 = fmaf(q1.w, kv[4 + i].w, d1);
            d2 = fmaf(q2.w, kv[8 + i].w, d2);
            d3 = fmaf(q3.w, kv[12 + i].w, d3);
        }
        srow[(size_t)u * LL] = ((d0 + d1) + (d2 + d3)) * scale;
    }
}

// ============================================================================
// kC2: in-place softmax over k for each (b,u) row. One block per row.
// ============================================================================
__global__ __launch_bounds__(256) void kC2() {
    __shared__ float red[256];
    int t = threadIdx.x;
    float* row = d_scores + (size_t)blockIdx.x * LL;

    float vreg[16];
    float mx = NEG_INF;
#pragma unroll
    for (int i = 0; i < 16; i++) {
        vreg[i] = row[t + i * 256];
        mx = fmaxf(mx, vreg[i]);
    }
    red[t] = mx;
    __syncthreads();
#pragma unroll
    for (int o = 128; o > 0; o >>= 1) {
        if (t < o) red[t] = fmaxf(red[t], red[t + o]);
        __syncthreads();
    }
    float m = red[0];
    __syncthreads();

    float s = 0.0f;
#pragma unroll
    for (int i = 0; i < 16; i++) {
        vreg[i] = __expf(vreg[i] - m);
        s += vreg[i];
    }
    red[t] = s;
    __syncthreads();
#pragma unroll
    for (int o = 128; o > 0; o >>= 1) {
        if (t < o) red[t] += red[t + o];
        __syncthreads();
    }
    float inv = 1.0f / red[0];
#pragma unroll
    for (int i = 0; i < 16; i++) row[t + i * 256] = vreg[i] * inv;
}

// ============================================================================
// kC3: partial upd[kt][b,u,e] over a contiguous k-range; deterministic smem
// reduction across the 4 kg groups. Pure FMA streaming.
// ============================================================================
__global__ __launch_bounds__(256) void kC3(const float* __restrict__ v) {
    __shared__ float sred[SS * EE];
    int b = blockIdx.x;
    int t = threadIdx.x;
    int e = t & 63, kg = t >> 6;
    int kbase = blockIdx.y * (LL / NKT) + kg * 256;

    const float* attn = d_scores + (size_t)b * SS * LL;
    const float* vb = v + (size_t)b * LL * EE;

    float acc[SS];
#pragma unroll
    for (int u = 0; u < SS; u++) acc[u] = 0.0f;

    for (int kb2 = 0; kb2 < 256; kb2 += 4) {
        int k0 = kbase + kb2;
        float vv0 = vb[(size_t)(k0 + 0) * EE + e];
        float vv1 = vb[(size_t)(k0 + 1) * EE + e];
        float vv2 = vb[(size_t)(k0 + 2) * EE + e];
        float vv3 = vb[(size_t)(k0 + 3) * EE + e];
#pragma unroll
        for (int u = 0; u < SS; u++) {
            float4 a4 = *reinterpret_cast<const float4*>(&attn[(size_t)u * LL + k0]);
            float r = acc[u];
            r = fmaf(a4.x, vv0, r);
            r = fmaf(a4.y, vv1, r);
            r = fmaf(a4.z, vv2, r);
            r = fmaf(a4.w, vv3, r);
            acc[u] = r;
        }
    }

    if (kg == 0) {
#pragma unroll
        for (int u = 0; u < SS; u++) sred[u * 64 + e] = acc[u];
    }
    __syncthreads();
    for (int r = 1; r < 4; r++) {
        if (kg == r) {
#pragma unroll
            for (int u = 0; u < SS; u++) sred[u * 64 + e] += acc[u];
        }
        __syncthreads();
    }
    float* outp = d_updp + (((size_t)blockIdx.y * BB + b) * SS) * EE;
    for (int i = t; i < SS * EE; i += 256) outp[i] = sred[i];
}

// ============================================================================
// kD1: per-tile column sums of values (scan phase 1).
// ============================================================================
__global__ __launch_bounds__(256) void kD1(const float* __restrict__ v) {
    __shared__ float sred[2 * EE];
    int b = blockIdx.x, tile = blockIdx.y, t = threadIdx.x;
    int e = t & 63, g = t >> 6;
    const float* vp = v + ((size_t)b * LL + tile * TILE + g * (TILE / 4)) * EE + e;

    float s = 0.0f;
#pragma unroll 8
    for (int i = 0; i < TILE / 4; i++) s += vp[(size_t)i * EE];
    if (g >= 2) sred[(g - 2) * EE + e] = s;
    __syncthreads();
    if (g < 2) sred[g * EE + e] += s;
    __syncthreads();
    if (g == 0) {
        float tot = sred[e] + sred[EE + e];
        d_tsum[((size_t)b * NT + tile) * EE + e] = tot;
    }
}

// ============================================================================
// kD2: exclusive scan of tile sums (scan phase 2). grid BB, 64 threads.
// ============================================================================
__global__ __launch_bounds__(64) void kD2() {
    int b = blockIdx.x, e = threadIdx.x;
    float acc = 0.0f;
    for (int tt = 0; tt < NT; tt++) {
        float s = d_tsum[((size_t)b * NT + tt) * EE + e];
        d_toff[((size_t)b * NT + tt) * EE + e] = acc;
        acc += s;
    }
}

// ============================================================================
// kD3: within-tile inclusive scan + precomputed offset -> out.
// ============================================================================
__global__ __launch_bounds__(64) void kD3(const float* __restrict__ v,
                                          float* __restrict__ out) {
    int b = blockIdx.x, tile = blockIdx.y, e = threadIdx.x;

    float acc = d_toff[((size_t)b * NT + tile) * EE + e];

    const float* vp = v + ((size_t)b * LL + tile * TILE) * EE + e;
    float* op = out + ((size_t)b * LL + tile * TILE) * EE + e;

    for (int i = 0; i < TILE; i += 8) {
        float x[8];
#pragma unroll
        for (int j = 0; j < 8; j++) x[j] = vp[(size_t)(i + j) * EE];
#pragma unroll
        for (int j = 0; j < 8; j++) { acc += x[j]; x[j] = acc; }
#pragma unroll
        for (int j = 0; j < 8; j++) op[(size_t)(i + j) * EE] = x[j];
    }
}

// ============================================================================
// kE: sum the NKT upd partials and scatter into out at the top-k rows.
// ============================================================================
__global__ __launch_bounds__(64) void kE(float* __restrict__ out) {
    int bu = blockIdx.x;
    int b = bu / SS, u = bu % SS;
    int e = threadIdx.x;
    int row = d_Mtop[b * 64 + u];

    float s = 0.0f;
#pragma unroll
    for (int kt = 0; kt < NKT; kt++)
        s += d_updp[(((size_t)kt * BB + b) * SS + u) * EE + e];

    out[((size_t)b * LL + row) * EE + e] = s;
}

// ============================================================================
extern "C" void kernel_launch(void* const* d_in, const int* in_sizes, int n_in,
                              void* d_out, int out_size) {
    const float* q   = (const float*)d_in[0];
    const float* k   = (const float*)d_in[1];
    const float* v   = (const float*)d_in[2];
    const int*   idx = (const int*)d_in[3];
    float* out = (float*)d_out;

    const int smemA2 = CROWS * KPAD * 4;   // 69632 bytes -> 2 CTAs/SM
    static int cfg_done = 0;
    if (!cfg_done) {
        cudaFuncSetAttribute(kA2, cudaFuncAttributeMaxDynamicSharedMemorySize,
                             smemA2);
        cfg_done = 1;
    }

    static cudaStream_t sD = nullptr;
    static cudaEvent_t  evFork = nullptr, evJoin = nullptr;
    if (!sD) {
        cudaStreamCreateWithFlags(&sD, cudaStreamNonBlocking);
        cudaEventCreateWithFlags(&evFork, cudaEventDisableTiming);
        cudaEventCreateWithFlags(&evJoin, cudaEventDisableTiming);
    }

    // Fork the independent cumsum chain at launch start: it overlaps the tiny
    // latency-bound P-phase kernels and finishes around when kA2 starts.
    cudaEventRecord(evFork, 0);
    cudaStreamWaitEvent(sD, evFork, 0);
    kD1<<<dim3(BB, NT), 256, 0, sD>>>(v);
    kD2<<<BB, 64, 0, sD>>>();
    kD3<<<dim3(BB, NT), 64, 0, sD>>>(v, out);
    cudaEventRecord(evJoin, sD);

    // Main chain.
    kP1<<<LL / 256, 256>>>(idx);
    kP2<<<NCH, 1024>>>();
    kP3<<<LL / 256, 256>>>(idx);
    kS<<<NCH, 512>>>();
    kA2<<<dim3(NCH, BB, 2), 512, smemA2>>>(q, k);
    kB<<<BB, 1024>>>();
    kC1<<<dim3(LL / 128, BB), 128>>>(q, k);
    kC2<<<BB * SS, 256>>>();
    kC3<<<dim3(BB, NKT), 256>>>(v);

    cudaStreamWaitEvent(0, evJoin, 0);
    kE<<<BB * SS, 64>>>(out);
}